// round 1
// baseline (speedup 1.0000x reference)
#include <cuda_runtime.h>

// ---------------- problem constants ----------------
constexpr int B_   = 64;
constexpr int T_   = 12;
constexpr int N_   = 325;
constexpr int H_   = 64;
constexpr int E_   = 32;
constexpr int LH_  = 128;
constexpr int OUT_ = 12;
constexpr int C_   = 97;   // 1 + 64 + 32 channels per (b,t,n)
constexpr int MOFF = 65;

constexpr int ROWS = 32;                         // n-rows per block
constexpr int NBLK = (N_ + ROWS - 1) / ROWS;     // 11

// ---------------- scratch (device globals; no mallocs allowed) ----------------
__device__ float  g_meta[B_ * E_];
// Wh packed for the LSTM inner loop:
//   g_WhA[b][ip*64 + j] = { W0[2ip][j], W0[2ip+1][j], W1[2ip][j], W1[2ip+1][j] }
//   g_WhB same for gates 2,3.   (i = input index, j = output index)
__device__ float4 g_WhA[B_][32 * 64];
__device__ float4 g_WhB[B_][32 * 64];
__device__ float  g_Wx[B_ * H_ * 4];   // [b][j][g]
__device__ float  g_Bb[B_ * H_ * 4];   // [b][j][g]

// ---------------- helpers ----------------
__device__ __forceinline__ unsigned long long pack2(float lo, float hi) {
    unsigned long long r;
    asm("mov.b64 %0, {%1,%2};" : "=l"(r) : "f"(lo), "f"(hi));
    return r;
}
__device__ __forceinline__ float hadd2(unsigned long long v) {
    float lo, hi;
    asm("mov.b64 {%0,%1}, %2;" : "=f"(lo), "=f"(hi) : "l"(v));
    return lo + hi;
}
__device__ __forceinline__ void fma2(unsigned long long& d,
                                     unsigned long long a,
                                     unsigned long long b) {
    asm("fma.rn.f32x2 %0, %1, %2, %0;" : "+l"(d) : "l"(a), "l"(b));
}
__device__ __forceinline__ float ex2a(float x) {
    float r; asm("ex2.approx.f32 %0, %1;" : "=f"(r) : "f"(x)); return r;
}
__device__ __forceinline__ float rcpa(float x) {
    float r; asm("rcp.approx.f32 %0, %1;" : "=f"(r) : "f"(x)); return r;
}
__device__ __forceinline__ float sig_a(float x) {
    // 1/(1+e^-x); abs err ~1e-7
    return rcpa(1.0f + ex2a(-1.4426950408889634f * x));
}
__device__ __forceinline__ float tanh_a(float x) {
    // 1 - 2/(e^{2x}+1); small-x safe (error is relative-of-0.5 -> ~1e-7 abs)
    float e = ex2a(2.8853900817779268f * x);
    return fmaf(-2.0f, rcpa(e + 1.0f), 1.0f);
}

// ---------------- kernel 1: meta = mean over T of x[:, :, 0, 65:] ----------------
__global__ void meta_kernel(const float* __restrict__ x) {
    int b = blockIdx.x, e = threadIdx.x;
    float s = 0.f;
#pragma unroll
    for (int t = 0; t < T_; t++)
        s += x[(size_t)((b * T_ + t) * N_) * C_ + MOFF + e];
    g_meta[b * E_ + e] = s * (1.0f / 12.0f);
}

// ---------------- kernel 2: the three meta-MLPs ----------------
// mode 0 -> Wx (O=64), mode 1 -> Wh (O=4096, packed layout), mode 2 -> bias (O=64)
__global__ void mlp_kernel(const float* __restrict__ W1, const float* __restrict__ b1,
                           const float* __restrict__ W2, const float* __restrict__ b2,
                           int O, int mode) {
    int g = blockIdx.x >> 6, b = blockIdx.x & 63;
    __shared__ float hsm[LH_];
    __shared__ float msm[E_];
    int tid = threadIdx.x;
    if (tid < E_) msm[tid] = g_meta[b * E_ + tid];
    __syncthreads();
    float acc = b1[g * LH_ + tid];
#pragma unroll
    for (int e = 0; e < E_; e++)
        acc = fmaf(msm[e], W1[(g * E_ + e) * LH_ + tid], acc);
    hsm[tid] = fmaxf(acc, 0.f);
    __syncthreads();
    for (int o = tid; o < O; o += LH_) {
        float a2 = b2[g * O + o];
#pragma unroll 16
        for (int l = 0; l < LH_; l++)
            a2 = fmaf(hsm[l], W2[(g * LH_ + l) * O + o], a2);
        if (mode == 0) {
            g_Wx[(b * H_ + o) * 4 + g] = a2;
        } else if (mode == 2) {
            g_Bb[(b * H_ + o) * 4 + g] = a2;
        } else {
            int i = o >> 6, j = o & 63;            // o = i*64 + j
            float* base = (g < 2) ? (float*)g_WhA[b] : (float*)g_WhB[b];
            base[(((i >> 1) * 64) + j) * 4 + ((g & 1) << 1) + (i & 1)] = a2;
        }
    }
}

// ---------------- kernel 3: LSTM recurrence + output head ----------------
struct SM {
    float4 WA[32 * 64];   // 32 KB  gates 0,1
    float4 WB[32 * 64];   // 32 KB  gates 2,3
    float  h[ROWS][H_];   // 8 KB
    float  x[ROWS][T_];   // 1.5 KB
};

__global__ void __launch_bounds__(256, 2)
lstm_kernel(const float* __restrict__ x,
            const float* __restrict__ fc1W, const float* __restrict__ fc1b,
            const float* __restrict__ fc2W, const float* __restrict__ fc2b,
            float* __restrict__ out) {
    extern __shared__ char smraw[];
    SM* s = (SM*)smraw;
    int b  = blockIdx.y;
    int n0 = blockIdx.x * ROWS;
    int tid = threadIdx.x;

    // stage per-batch Wh into smem (coalesced 16B copies)
    const float4* srcA = g_WhA[b];
    const float4* srcB = g_WhB[b];
    for (int i = tid; i < 32 * 64; i += 256) { s->WA[i] = srcA[i]; s->WB[i] = srcB[i]; }
    // stage x signal tile
    for (int i = tid; i < ROWS * T_; i += 256) {
        int r = i / T_, t = i - r * T_;
        int n = n0 + r;
        s->x[r][t] = (n < N_) ? x[(size_t)((b * T_ + t) * N_ + n) * C_] : 0.f;
    }
    for (int i = tid; i < ROWS * H_; i += 256) ((float*)s->h)[i] = 0.f;

    int w = tid >> 5, lane = tid & 31;
    int j  = ((w & 1) << 5) | lane;   // this thread's output index (0..63)
    int r0 = (w >> 1) * 8;            // this thread's row-group base (8 rows)

    float4 wx4 = *(const float4*)&g_Wx[(b * H_ + j) * 4];
    float4 bi4 = *(const float4*)&g_Bb[(b * H_ + j) * 4];
    __syncthreads();

    float c[8];
#pragma unroll
    for (int r = 0; r < 8; r++) c[r] = 0.f;

    for (int t = 0; t < T_; t++) {
        unsigned long long z0[8], z1[8], z2[8], z3[8];
#pragma unroll
        for (int r = 0; r < 8; r++) {
            float xv = s->x[r0 + r][t];
            float zf = 0.f;
            z0[r] = pack2(fmaf(xv, wx4.x, bi4.x), zf);
            z1[r] = pack2(fmaf(xv, wx4.y, bi4.y), zf);
            z2[r] = pack2(fmaf(xv, wx4.z, bi4.z), zf);
            z3[r] = pack2(fmaf(xv, wx4.w, bi4.w), zf);
        }
        // reduction over input index i, two i's at a time via f32x2
#pragma unroll 8
        for (int ip = 0; ip < 32; ip++) {
            ulonglong2 a  = *(const ulonglong2*)&s->WA[ip * 64 + j];
            ulonglong2 bb = *(const ulonglong2*)&s->WB[ip * 64 + j];
#pragma unroll
            for (int r = 0; r < 8; r++) {
                unsigned long long hp =
                    *(const unsigned long long*)&s->h[r0 + r][2 * ip];
                fma2(z0[r], a.x,  hp);
                fma2(z1[r], a.y,  hp);
                fma2(z2[r], bb.x, hp);
                fma2(z3[r], bb.y, hp);
            }
        }
        __syncthreads();   // everyone done reading h before we overwrite it
#pragma unroll
        for (int r = 0; r < 8; r++) {
            float zg = hadd2(z0[r]);
            float zi = hadd2(z1[r]);
            float zf = hadd2(z2[r]);
            float zo = hadd2(z3[r]);
            float gg = tanh_a(zg);
            float ii = sig_a(zi);
            float ff = sig_a(zf);
            float oo = sig_a(zo);
            float cc = fmaf(gg, ii, c[r] * ff);
            c[r] = cc;
            s->h[r0 + r][j] = tanh_a(cc) * oo;
        }
        __syncthreads();   // h fully written before next step reads it
    }

    // ---- output head: relu(h) @ fc1 -> relu -> @ fc2 ----
    // warp w handles rows {w, w+8, w+16, w+24}
#pragma unroll
    for (int q = 0; q < 4; q++) {
        int row = w + 8 * q;
        int n = n0 + row;
        float acc = fc1b[lane];
#pragma unroll 16
        for (int i = 0; i < 64; i++) {
            float hv = fmaxf(s->h[row][i], 0.f);
            acc = fmaf(hv, fc1W[i * 32 + lane], acc);
        }
        float o1 = fmaxf(acc, 0.f);
        float acc2 = (lane < OUT_) ? fc2b[lane] : 0.f;
#pragma unroll
        for (int jj = 0; jj < 32; jj++) {
            float v  = __shfl_sync(0xffffffffu, o1, jj);
            float wv = (lane < OUT_) ? fc2W[jj * OUT_ + lane] : 0.f;
            acc2 = fmaf(v, wv, acc2);
        }
        if (lane < OUT_ && n < N_)
            out[(size_t)(b * OUT_ + lane) * N_ + n] = acc2;
    }
}

// ---------------- launcher ----------------
extern "C" void kernel_launch(void* const* d_in, const int* in_sizes, int n_in,
                              void* d_out, int out_size) {
    const float* x      = (const float*)d_in[0];
    const float* lwx_W1 = (const float*)d_in[1];
    const float* lwx_b1 = (const float*)d_in[2];
    const float* lwx_W2 = (const float*)d_in[3];
    const float* lwx_b2 = (const float*)d_in[4];
    const float* lwh_W1 = (const float*)d_in[5];
    const float* lwh_b1 = (const float*)d_in[6];
    const float* lwh_W2 = (const float*)d_in[7];
    const float* lwh_b2 = (const float*)d_in[8];
    const float* lb_W1  = (const float*)d_in[9];
    const float* lb_b1  = (const float*)d_in[10];
    const float* lb_W2  = (const float*)d_in[11];
    const float* lb_b2  = (const float*)d_in[12];
    const float* fc1W   = (const float*)d_in[13];
    const float* fc1b   = (const float*)d_in[14];
    const float* fc2W   = (const float*)d_in[15];
    const float* fc2b   = (const float*)d_in[16];

    cudaFuncSetAttribute(lstm_kernel,
                         cudaFuncAttributeMaxDynamicSharedMemorySize,
                         (int)sizeof(SM));

    meta_kernel<<<B_, E_>>>(x);
    mlp_kernel<<<4 * B_, LH_>>>(lwx_W1, lwx_b1, lwx_W2, lwx_b2, H_, 0);
    mlp_kernel<<<4 * B_, LH_>>>(lwh_W1, lwh_b1, lwh_W2, lwh_b2, H_ * H_, 1);
    mlp_kernel<<<4 * B_, LH_>>>(lb_W1,  lb_b1,  lb_W2,  lb_b2,  H_, 2);

    dim3 grid(NBLK, B_);
    lstm_kernel<<<grid, 256, sizeof(SM)>>>(x, fc1W, fc1b, fc2W, fc2b,
                                           (float*)d_out);
}

// round 2
// speedup vs baseline: 1.1184x; 1.1184x over previous
#include <cuda_runtime.h>

// ---------------- problem constants ----------------
constexpr int B_   = 64;
constexpr int T_   = 12;
constexpr int N_   = 325;
constexpr int H_   = 64;
constexpr int E_   = 32;
constexpr int LH_  = 128;
constexpr int OUT_ = 12;
constexpr int C_   = 97;   // 1 + 64 + 32 channels
constexpr int MOFF = 65;

constexpr int ROWS = 40;                         // n-rows per block
constexpr int NBLK = (N_ + ROWS - 1) / ROWS;     // 9  -> grid 576 = 1.95 waves
constexpr int THR  = 320;                        // 64 j x 5 row-groups of 8

// ---------------- scratch (device globals) ----------------
__device__ float  g_hid[3 * 4 * B_ * LH_];       // stage-1 hidden activations
// Wh packed: g_WhA[b][ip*64+j] = {W0[2ip][j],W0[2ip+1][j],W1[2ip][j],W1[2ip+1][j]}
__device__ float4 g_WhA[B_][32 * 64];
__device__ float4 g_WhB[B_][32 * 64];
__device__ float  g_Wx[B_ * H_ * 4];             // [b][j][g]
__device__ float  g_Bb[B_ * H_ * 4];             // [b][j][g]

// ---------------- helpers ----------------
__device__ __forceinline__ unsigned long long pack2(float lo, float hi) {
    unsigned long long r;
    asm("mov.b64 %0, {%1,%2};" : "=l"(r) : "f"(lo), "f"(hi));
    return r;
}
__device__ __forceinline__ float hadd2(unsigned long long v) {
    float lo, hi;
    asm("mov.b64 {%0,%1}, %2;" : "=f"(lo), "=f"(hi) : "l"(v));
    return lo + hi;
}
__device__ __forceinline__ void fma2(unsigned long long& d,
                                     unsigned long long a,
                                     unsigned long long b) {
    asm("fma.rn.f32x2 %0, %1, %2, %0;" : "+l"(d) : "l"(a), "l"(b));
}
__device__ __forceinline__ float ex2a(float x) {
    float r; asm("ex2.approx.f32 %0, %1;" : "=f"(r) : "f"(x)); return r;
}
__device__ __forceinline__ float rcpa(float x) {
    float r; asm("rcp.approx.f32 %0, %1;" : "=f"(r) : "f"(x)); return r;
}
__device__ __forceinline__ float sig_a(float x) {
    return rcpa(1.0f + ex2a(-1.4426950408889634f * x));
}
__device__ __forceinline__ float tanh_a(float x) {
    float e = ex2a(2.8853900817779268f * x);
    return fmaf(-2.0f, rcpa(e + 1.0f), 1.0f);
}

// ============ stage 1: meta + first MLP layer, all 3 MLPs, all 4 gates ============
// grid = 3*64 blocks (m, b), 128 threads
__global__ void stage1_kernel(const float* __restrict__ x,
                              const float* __restrict__ wxW1, const float* __restrict__ wxB1,
                              const float* __restrict__ whW1, const float* __restrict__ whB1,
                              const float* __restrict__ lbW1, const float* __restrict__ lbB1) {
    int m = blockIdx.x >> 6, b = blockIdx.x & 63;
    const float* W1 = (m == 0) ? wxW1 : (m == 1) ? whW1 : lbW1;
    const float* b1 = (m == 0) ? wxB1 : (m == 1) ? whB1 : lbB1;
    __shared__ float meta[E_];
    int tid = threadIdx.x;
    if (tid < E_) {
        float s = 0.f;
#pragma unroll
        for (int t = 0; t < T_; t++)
            s += x[(size_t)((b * T_ + t) * N_) * C_ + MOFF + tid];
        meta[tid] = s * (1.0f / 12.0f);
    }
    __syncthreads();
#pragma unroll
    for (int g = 0; g < 4; g++) {
        float acc = b1[g * LH_ + tid];
#pragma unroll
        for (int e = 0; e < E_; e++)
            acc = fmaf(meta[e], W1[(g * E_ + e) * LH_ + tid], acc);
        g_hid[((m * 4 + g) * B_ + b) * LH_ + tid] = fmaxf(acc, 0.f);
    }
}

// ============ stage 2: second MLP layer as batched GEMM ============
// grid = 4 gates * 66 tiles (64 Wh o-tiles + 1 Wx + 1 bias), 256 threads
// thread = (bg, o): bg = tid>>6 (16 batches each), o = tid&63
__global__ void stage2_kernel(const float* __restrict__ wxW2, const float* __restrict__ wxB2,
                              const float* __restrict__ whW2, const float* __restrict__ whB2,
                              const float* __restrict__ lbW2, const float* __restrict__ lbB2) {
    __shared__ float hs[B_ * LH_];    // 32KB
    __shared__ float w2[LH_ * 64];    // 32KB
    int g  = blockIdx.x / 66;
    int tl = blockIdx.x % 66;
    int m  = (tl < 64) ? 1 : (tl == 64 ? 0 : 2);
    int tile = (m == 1) ? tl : 0;
    int tid = threadIdx.x;
    int o = tid & 63, bg = tid >> 6;

    // stage hidden activations (contiguous)
    const float* hsrc = g_hid + (m * 4 + g) * (B_ * LH_);
    for (int i = tid; i < B_ * LH_; i += 256) hs[i] = hsrc[i];
    // stage W2 tile
    const float* W2; const float* b2; int ostride;
    if (m == 1)      { W2 = whW2 + g * LH_ * 4096 + tile * 64; b2 = whB2 + g * 4096 + tile * 64; ostride = 4096; }
    else if (m == 0) { W2 = wxW2 + g * LH_ * 64;               b2 = wxB2 + g * 64;               ostride = 64; }
    else             { W2 = lbW2 + g * LH_ * 64;               b2 = lbB2 + g * 64;               ostride = 64; }
    for (int i = tid; i < LH_ * 64; i += 256) {
        int k = i >> 6, oo = i & 63;
        w2[i] = W2[k * ostride + oo];
    }
    __syncthreads();

    float bv = b2[o];
    float acc[16];
#pragma unroll
    for (int i = 0; i < 16; i++) acc[i] = bv;
    const float* hb = hs + bg * 16 * LH_;
#pragma unroll 4
    for (int k = 0; k < LH_; k++) {
        float w = w2[k * 64 + o];
#pragma unroll
        for (int i = 0; i < 16; i++)
            acc[i] = fmaf(hb[i * LH_ + k], w, acc[i]);
    }

#pragma unroll
    for (int i = 0; i < 16; i++) {
        int b = bg * 16 + i;
        if (m == 0)      g_Wx[(b * H_ + o) * 4 + g] = acc[i];
        else if (m == 2) g_Bb[(b * H_ + o) * 4 + g] = acc[i];
        else {
            float* base = (g < 2) ? (float*)g_WhA[b] : (float*)g_WhB[b];
            base[(((tile >> 1) * 64) + o) * 4 + ((g & 1) << 1) + (tile & 1)] = acc[i];
        }
    }
}

// ============ stage 3: LSTM recurrence + output head ============
struct SMEM {
    float4 WA[32 * 64];        // 32 KB  gates 0,1
    float4 WB[32 * 64];        // 32 KB  gates 2,3
    float  h[2][ROWS][H_];     // 20 KB  double-buffered
    float  xs[ROWS][T_];       // 1.875 KB
    float4 wx[H_];             // 1 KB
    float4 bi[H_];             // 1 KB
};

__global__ void __launch_bounds__(THR, 2)
lstm_kernel(const float* __restrict__ x,
            const float* __restrict__ fc1W, const float* __restrict__ fc1b,
            const float* __restrict__ fc2W, const float* __restrict__ fc2b,
            float* __restrict__ out) {
    extern __shared__ char smraw[];
    SMEM* s = (SMEM*)smraw;
    int b  = blockIdx.y;
    int n0 = blockIdx.x * ROWS;
    int tid = threadIdx.x;

    const float4* srcA = g_WhA[b];
    const float4* srcB = g_WhB[b];
    for (int i = tid; i < 32 * 64; i += THR) { s->WA[i] = srcA[i]; s->WB[i] = srcB[i]; }
    for (int i = tid; i < ROWS * T_; i += THR) {
        int r = i / T_, t = i - r * T_;
        int n = n0 + r;
        s->xs[r][t] = (n < N_) ? x[(size_t)((b * T_ + t) * N_ + n) * C_] : 0.f;
    }
    for (int i = tid; i < ROWS * H_; i += THR) ((float*)s->h[0])[i] = 0.f;
    if (tid < H_) {
        s->wx[tid] = *(const float4*)&g_Wx[(b * H_ + tid) * 4];
        s->bi[tid] = *(const float4*)&g_Bb[(b * H_ + tid) * 4];
    }
    __syncthreads();

    int w = tid >> 5, lane = tid & 31;
    int j  = ((w & 1) << 5) | lane;   // output index 0..63
    int r0 = (w >> 1) * 8;            // row-group base (8 rows)

    float c[8];
#pragma unroll
    for (int r = 0; r < 8; r++) c[r] = 0.f;

    int p = 0;
    for (int t = 0; t < T_; t++) {
        float4 wx4 = s->wx[j];
        float4 bi4 = s->bi[j];
        unsigned long long z0[8], z1[8], z2[8], z3[8];
#pragma unroll
        for (int r = 0; r < 8; r++) {
            float xv = s->xs[r0 + r][t];
            z0[r] = pack2(fmaf(xv, wx4.x, bi4.x), 0.f);
            z1[r] = pack2(fmaf(xv, wx4.y, bi4.y), 0.f);
            z2[r] = pack2(fmaf(xv, wx4.z, bi4.z), 0.f);
            z3[r] = pack2(fmaf(xv, wx4.w, bi4.w), 0.f);
        }
        const float* hbase = &s->h[p][0][0];
#pragma unroll 8
        for (int ip = 0; ip < 32; ip++) {
            ulonglong2 a  = *(const ulonglong2*)&s->WA[ip * 64 + j];
            ulonglong2 bb = *(const ulonglong2*)&s->WB[ip * 64 + j];
#pragma unroll
            for (int r = 0; r < 8; r++) {
                unsigned long long hp =
                    *(const unsigned long long*)&hbase[(r0 + r) * H_ + 2 * ip];
                fma2(z0[r], a.x,  hp);
                fma2(z1[r], a.y,  hp);
                fma2(z2[r], bb.x, hp);
                fma2(z3[r], bb.y, hp);
            }
        }
#pragma unroll
        for (int r = 0; r < 8; r++) {
            float gg = tanh_a(hadd2(z0[r]));
            float ii = sig_a(hadd2(z1[r]));
            float ff = sig_a(hadd2(z2[r]));
            float oo = sig_a(hadd2(z3[r]));
            float cc = fmaf(gg, ii, c[r] * ff);
            c[r] = cc;
            s->h[p ^ 1][r0 + r][j] = tanh_a(cc) * oo;
        }
        __syncthreads();   // single barrier: writes of t visible, reads of t done
        p ^= 1;
    }

    // ---- output head: relu(h) @ fc1 -> relu -> @ fc2 ----
#pragma unroll
    for (int q = 0; q < 4; q++) {
        int row = w + 10 * q;
        int n = n0 + row;
        float acc = fc1b[lane];
#pragma unroll 16
        for (int i = 0; i < 64; i++) {
            float hv = fmaxf(s->h[p][row][i], 0.f);
            acc = fmaf(hv, fc1W[i * 32 + lane], acc);
        }
        float o1 = fmaxf(acc, 0.f);
        float acc2 = (lane < OUT_) ? fc2b[lane] : 0.f;
#pragma unroll
        for (int jj = 0; jj < 32; jj++) {
            float v  = __shfl_sync(0xffffffffu, o1, jj);
            float wv = (lane < OUT_) ? fc2W[jj * OUT_ + lane] : 0.f;
            acc2 = fmaf(v, wv, acc2);
        }
        if (lane < OUT_ && n < N_)
            out[(size_t)(b * OUT_ + lane) * N_ + n] = acc2;
    }
}

// ---------------- launcher ----------------
extern "C" void kernel_launch(void* const* d_in, const int* in_sizes, int n_in,
                              void* d_out, int out_size) {
    const float* x      = (const float*)d_in[0];
    const float* lwx_W1 = (const float*)d_in[1];
    const float* lwx_b1 = (const float*)d_in[2];
    const float* lwx_W2 = (const float*)d_in[3];
    const float* lwx_b2 = (const float*)d_in[4];
    const float* lwh_W1 = (const float*)d_in[5];
    const float* lwh_b1 = (const float*)d_in[6];
    const float* lwh_W2 = (const float*)d_in[7];
    const float* lwh_b2 = (const float*)d_in[8];
    const float* lb_W1  = (const float*)d_in[9];
    const float* lb_b1  = (const float*)d_in[10];
    const float* lb_W2  = (const float*)d_in[11];
    const float* lb_b2  = (const float*)d_in[12];
    const float* fc1W   = (const float*)d_in[13];
    const float* fc1b   = (const float*)d_in[14];
    const float* fc2W   = (const float*)d_in[15];
    const float* fc2b   = (const float*)d_in[16];

    cudaFuncSetAttribute(lstm_kernel,
                         cudaFuncAttributeMaxDynamicSharedMemorySize,
                         (int)sizeof(SMEM));

    stage1_kernel<<<3 * B_, LH_>>>(x, lwx_W1, lwx_b1, lwh_W1, lwh_b1, lb_W1, lb_b1);
    stage2_kernel<<<4 * 66, 256>>>(lwx_W2, lwx_b2, lwh_W2, lwh_b2, lb_W2, lb_b2);

    dim3 grid(NBLK, B_);
    lstm_kernel<<<grid, THR, sizeof(SMEM)>>>(x, fc1W, fc1b, fc2W, fc2b,
                                             (float*)d_out);
}